// round 12
// baseline (speedup 1.0000x reference)
#include <cuda_runtime.h>

#define B_ 2
#define F_ 128
#define N_ 192
#define S_ 192
#define H_ 4
#define D_ 64
#define HD_ 256
#define LOG2E 1.4426950408889634f

// SS[bh][i][s] = log2e*(s_src + q_src + b_attn), masked to -1e30 where A[s,i]==0
// SDT[bh][j][s] = log2e*(s_dst + q_dst)   (j-major for coalesced column reads)
static __device__ __align__(16) float d_SS [B_*H_*N_*S_];
static __device__ __align__(16) float d_SDT[B_*H_*N_*S_];
static __device__ float d_P[F_*8];
static __device__ float d_Q[8];
static __device__ float d_colsum2[B_*F_*2];
static __device__ float d_sumg[HD_];

__device__ __forceinline__ float ex2f(float x){ float r; asm("ex2.approx.ftz.f32 %0, %1;" : "=f"(r) : "f"(x)); return r; }
__device__ __forceinline__ float rcpf(float x){ float r; asm("rcp.approx.ftz.f32 %0, %1;" : "=f"(r) : "f"(x)); return r; }

// ---- launch 1: colsum half-slices (blocks 0..511) + W_attn folding (blocks 512..515) ----
__global__ void __launch_bounds__(256) k_colsum(const float* __restrict__ X,
                                                const float* __restrict__ Wl,
                                                const float* __restrict__ bl,
                                                const float* __restrict__ Wa,
                                                const float* __restrict__ ba){
    int t = threadIdx.x;
    if (blockIdx.x >= 512){
        int fblk = blockIdx.x - 512;
        if (t < 128){
            int f = fblk*32 + (t >> 2), h = t & 3;
            float ps = 0.f, pd = 0.f;
            #pragma unroll 8
            for (int d = 0; d < D_; ++d){
                float wl = Wl[f*HD_ + h*D_ + d];
                ps += wl * Wa[d];
                pd += wl * Wa[D_ + d];
            }
            d_P[f*8 + h]     = ps * LOG2E;
            d_P[f*8 + 4 + h] = pd * LOG2E;
        }
        if (fblk == 0 && t < 8){
            int which = t >> 2, hh = t & 3;
            float q = 0.f;
            for (int d = 0; d < D_; ++d) q += bl[hh*D_ + d] * Wa[which*D_ + d];
            if (which == 0) q += ba[0];
            d_Q[which*4 + hh] = q * LOG2E;
        }
        return;
    }
    int cb   = blockIdx.x;            // 512 half-slices
    int bf   = cb >> 1;
    int half = cb & 1;
    const float4* p = (const float4*)(X + (size_t)bf*(N_*S_) + half*(N_*S_/2));
    float acc = 0.f;
    #pragma unroll 6
    for (int i = t; i < (N_*S_)/8; i += 256){
        float4 v = __ldg(p + i);
        acc += (v.x + v.y) + (v.z + v.w);
    }
    unsigned m = 0xFFFFFFFFu;
    acc += __shfl_down_sync(m, acc, 16);
    acc += __shfl_down_sync(m, acc, 8);
    acc += __shfl_down_sync(m, acc, 4);
    acc += __shfl_down_sync(m, acc, 2);
    acc += __shfl_down_sync(m, acc, 1);
    __shared__ float wparts[8];
    if ((t & 31) == 0) wparts[t >> 5] = acc;
    __syncthreads();
    if (t == 0){
        float s = 0.f;
        #pragma unroll
        for (int k = 0; k < 8; ++k) s += wparts[k];
        d_colsum2[cb] = s;
    }
}

// ---- launch 2: projection (blocks 0..767) + sum_g (block 768) ----
__global__ void __launch_bounds__(384, 4) k_proj(const float* __restrict__ X,
                                                 const int* __restrict__ A,
                                                 const float* __restrict__ Wl,
                                                 const float* __restrict__ bl){
    int t  = threadIdx.x;
    if (blockIdx.x >= B_*N_*2){
        // sum_g[c] = colsumX · W_lin[:,c] + R*b_lin[c]   (256 threads used)
        __shared__ float cs[F_];
        if (t < F_)
            cs[t] = (d_colsum2[2*t] + d_colsum2[2*t+1])
                  + (d_colsum2[2*F_ + 2*t] + d_colsum2[2*F_ + 2*t+1]);
        __syncthreads();
        if (t < HD_){
            float acc = (float)(B_*N_*S_) * __ldg(bl + t);
            #pragma unroll
            for (int f0 = 0; f0 < F_; f0 += 16){
                float wv[16];
                #pragma unroll
                for (int k = 0; k < 16; ++k) wv[k] = __ldg(Wl + (f0+k)*HD_ + t);
                #pragma unroll
                for (int k = 0; k < 16; ++k) acc += cs[f0+k] * wv[k];
            }
            d_sumg[t] = acc;
        }
        return;
    }
    __shared__ float sP[F_*8];
    __shared__ float sQ[8];
    __shared__ float pacc[3][96][9];
    int blk = blockIdx.x;
    int b  = blk / (N_*2);
    int r  = blk % (N_*2);
    int n  = r >> 1;
    int sh = r & 1;
    for (int i = t; i < F_*8; i += 384) sP[i] = d_P[i];
    if (t < 8) sQ[t] = d_Q[t];
    __syncthreads();
    int sl = t % 96;
    int fg = t / 96;
    int s  = sh*96 + sl;
    int fb = fg*32;
    float acc[8];
    #pragma unroll
    for (int k = 0; k < 8; ++k) acc[k] = 0.f;
    const float* xp = X + ((size_t)(b*F_ + fb)*N_ + n)*S_ + s;
    #pragma unroll
    for (int f0 = 0; f0 < 32; f0 += 16){
        float xv[16];
        #pragma unroll
        for (int k = 0; k < 16; ++k) xv[k] = __ldg(xp + (size_t)(f0+k)*(N_*S_));
        #pragma unroll
        for (int k = 0; k < 16; ++k){
            const float* pr = sP + (fb+f0+k)*8;
            float4 p0 = *(const float4*)pr;
            float4 p1 = *(const float4*)(pr+4);
            acc[0] += xv[k]*p0.x; acc[1] += xv[k]*p0.y; acc[2] += xv[k]*p0.z; acc[3] += xv[k]*p0.w;
            acc[4] += xv[k]*p1.x; acc[5] += xv[k]*p1.y; acc[6] += xv[k]*p1.z; acc[7] += xv[k]*p1.w;
        }
    }
    if (fg > 0){
        #pragma unroll
        for (int k = 0; k < 8; ++k) pacc[fg-1][sl][k] = acc[k];
    }
    __syncthreads();
    if (fg == 0){
        #pragma unroll
        for (int g = 0; g < 3; ++g)
            #pragma unroll
            for (int k = 0; k < 8; ++k) acc[k] += pacc[g][sl][k];
        int av = A[s*N_ + n];   // mask A[s, i=n]
        #pragma unroll
        for (int h = 0; h < H_; ++h){
            int bh = b*H_ + h;
            float u = acc[h] + sQ[h];
            d_SS [((size_t)bh*N_ + n)*S_ + s] = av ? u : -1e30f;
            d_SDT[((size_t)bh*N_ + n)*S_ + s] = acc[4+h] + sQ[4+h];
        }
    }
}

// ---- launch 3: attention; CTA per (b,h,i-triple); warp owns 32 columns j ----
// lane s-map: {4l..4l+3} and {128+2l, 128+2l+1}; one V load feeds 3 i's
__global__ void __launch_bounds__(192) k_attn(float* __restrict__ out){
    __shared__ float w0[S_], w1[S_], w2[S_];
    __shared__ float AL[6][3][S_];
    __shared__ float sg[D_];

    int i0 = blockIdx.x * 3, h = blockIdx.y, b = blockIdx.z;
    int bh = b*H_ + h;
    int t  = threadIdx.x, lane = t & 31, wp = t >> 5;

    w0[t] = d_SS[((size_t)bh*N_ + i0    )*S_ + t];
    w1[t] = d_SS[((size_t)bh*N_ + i0 + 1)*S_ + t];
    w2[t] = d_SS[((size_t)bh*N_ + i0 + 2)*S_ + t];
    if (t < D_) sg[t] = d_sumg[h*D_ + t];
    __syncthreads();

    float wr0[6], wr1[6], wr2[6], acc0[6], acc1[6], acc2[6];
    {
        float4 a4 = *(const float4*)(w0 + 4*lane);
        float2 a2 = *(const float2*)(w0 + 128 + 2*lane);
        wr0[0]=a4.x; wr0[1]=a4.y; wr0[2]=a4.z; wr0[3]=a4.w; wr0[4]=a2.x; wr0[5]=a2.y;
        float4 b4 = *(const float4*)(w1 + 4*lane);
        float2 b2 = *(const float2*)(w1 + 128 + 2*lane);
        wr1[0]=b4.x; wr1[1]=b4.y; wr1[2]=b4.z; wr1[3]=b4.w; wr1[4]=b2.x; wr1[5]=b2.y;
        float4 c4 = *(const float4*)(w2 + 4*lane);
        float2 c2 = *(const float2*)(w2 + 128 + 2*lane);
        wr2[0]=c4.x; wr2[1]=c4.y; wr2[2]=c4.z; wr2[3]=c4.w; wr2[4]=c2.x; wr2[5]=c2.y;
    }
    #pragma unroll
    for (int k = 0; k < 6; ++k){ acc0[k] = 0.f; acc1[k] = 0.f; acc2[k] = 0.f; }

    const float* VT = d_SDT + (size_t)bh*N_*S_;
    const unsigned m = 0xFFFFFFFFu;

    #pragma unroll 2
    for (int jj = 0; jj < 32; ++jj){
        const float* vrow = VT + (size_t)(wp*32 + jj)*S_;
        float4 v4 = __ldg((const float4*)(vrow + 4*lane));
        float2 v2 = __ldg((const float2*)(vrow + 128 + 2*lane));
        float vr[6] = {v4.x, v4.y, v4.z, v4.w, v2.x, v2.y};
        float e0[6], e1[6], e2[6];
        float z0 = 0.f, z1 = 0.f, z2 = 0.f;
        #pragma unroll
        for (int k = 0; k < 6; ++k){
            float a = wr0[k] + vr[k];
            e0[k] = ex2f(fmaxf(a, 0.2f*a));
            z0 += e0[k];
            float c = wr1[k] + vr[k];
            e1[k] = ex2f(fmaxf(c, 0.2f*c));
            z1 += e1[k];
            float d = wr2[k] + vr[k];
            e2[k] = ex2f(fmaxf(d, 0.2f*d));
            z2 += e2[k];
        }
        // three independent shuffle chains, interleaved by the scheduler
        z0 += __shfl_xor_sync(m, z0, 16);  z1 += __shfl_xor_sync(m, z1, 16);  z2 += __shfl_xor_sync(m, z2, 16);
        z0 += __shfl_xor_sync(m, z0, 8);   z1 += __shfl_xor_sync(m, z1, 8);   z2 += __shfl_xor_sync(m, z2, 8);
        z0 += __shfl_xor_sync(m, z0, 4);   z1 += __shfl_xor_sync(m, z1, 4);   z2 += __shfl_xor_sync(m, z2, 4);
        z0 += __shfl_xor_sync(m, z0, 2);   z1 += __shfl_xor_sync(m, z1, 2);   z2 += __shfl_xor_sync(m, z2, 2);
        z0 += __shfl_xor_sync(m, z0, 1);   z1 += __shfl_xor_sync(m, z1, 1);   z2 += __shfl_xor_sync(m, z2, 1);
        float iz0 = rcpf(z0 + 1e-30f);   // all-masked column: e==0 -> 0
        float iz1 = rcpf(z1 + 1e-30f);
        float iz2 = rcpf(z2 + 1e-30f);
        #pragma unroll
        for (int k = 0; k < 6; ++k){
            acc0[k] += e0[k]*iz0;
            acc1[k] += e1[k]*iz1;
            acc2[k] += e2[k]*iz2;
        }
    }

    #pragma unroll
    for (int k = 0; k < 4; ++k){
        AL[wp][0][4*lane+k] = acc0[k];
        AL[wp][1][4*lane+k] = acc1[k];
        AL[wp][2][4*lane+k] = acc2[k];
    }
    AL[wp][0][128+2*lane]   = acc0[4];
    AL[wp][0][128+2*lane+1] = acc0[5];
    AL[wp][1][128+2*lane]   = acc1[4];
    AL[wp][1][128+2*lane+1] = acc1[5];
    AL[wp][2][128+2*lane]   = acc2[4];
    AL[wp][2][128+2*lane+1] = acc2[5];
    __syncthreads();
    w0[t] = ((AL[0][0][t]+AL[1][0][t]) + (AL[2][0][t]+AL[3][0][t])) + (AL[4][0][t]+AL[5][0][t]);
    w1[t] = ((AL[0][1][t]+AL[1][1][t]) + (AL[2][1][t]+AL[3][1][t])) + (AL[4][1][t]+AL[5][1][t]);
    w2[t] = ((AL[0][2][t]+AL[1][2][t]) + (AL[2][2][t]+AL[3][2][t])) + (AL[4][2][t]+AL[5][2][t]);
    __syncthreads();

    for (int idx = t; idx < 3*D_*(S_/4); idx += 192){
        int ii = idx / (D_*(S_/4));
        int r  = idx % (D_*(S_/4));
        int d  = r / (S_/4);
        int s4 = r % (S_/4);
        const float* ALp = (ii == 0) ? w0 : (ii == 1 ? w1 : w2);
        float4 a4 = *(const float4*)(ALp + s4*4);
        float sv = sg[d];
        float4 o = make_float4(a4.x*sv, a4.y*sv, a4.z*sv, a4.w*sv);
        *(float4*)(out + ((size_t)(b*HD_ + h*D_ + d)*N_ + i0 + ii)*S_ + s4*4) = o;
    }
}

extern "C" void kernel_launch(void* const* d_in, const int* in_sizes, int n_in,
                              void* d_out, int out_size){
    const float* X  = (const float*)d_in[0];
    const int*   A  = (const int*)  d_in[1];
    const float* Wl = (const float*)d_in[2];
    const float* bl = (const float*)d_in[3];
    const float* Wa = (const float*)d_in[4];
    const float* ba = (const float*)d_in[5];
    float* out = (float*)d_out;

    k_colsum<<<516, 256>>>(X, Wl, bl, Wa, ba);
    k_proj  <<<B_*N_*2 + 1, 384>>>(X, A, Wl, bl);
    dim3 g(N_/3, H_, B_);
    k_attn  <<<g, 192>>>(out);
}